// round 2
// baseline (speedup 1.0000x reference)
#include <cuda_runtime.h>
#include <math.h>

// ---------------------------------------------------------------------------
// GATv2Conv layer, fully fused. N=50000 nodes, E=800000 edges, D=128, H=4, C=32.
// Pipeline:
//   kdetect : int64 vs int32 edge_index sniffing (jax x64 ambiguity)
//   kzero   : zero per-dst degree histogram
//   khist   : degree histogram (int atomics)
//   kscan   : exclusive scan -> rowptr + cursor (single block)
//   kscatter: build dst-CSR edge permutation
//   k_gemm  : xl = x@Wl+bl, xr = x@Wr+br  (f32x2 packed FMA, smem-tiled)
//   k_fused : per-node: edge loop (e_feat matvec + leakyrelu + att dot +
//             exp + running num/den) -> softmax-free normalization ->
//             bias -> exact GELU -> residual -> warp LayerNorm -> store
// ---------------------------------------------------------------------------

#define MAX_N 50000
#define MAX_E 800000

typedef unsigned long long ull;

__device__ int   g_is64;
__device__ float g_xl[(size_t)MAX_N * 128];
__device__ float g_xr[(size_t)MAX_N * 128];
__device__ int   g_count[MAX_N];
__device__ int   g_rowptr[MAX_N + 1];
__device__ int   g_cursor[MAX_N];
__device__ int   g_eperm[MAX_E];

// ---- packed f32x2 helpers (Blackwell) ----
__device__ __forceinline__ ull pk(float lo, float hi) {
    ull r; asm("mov.b64 %0,{%1,%2};" : "=l"(r) : "f"(lo), "f"(hi)); return r;
}
__device__ __forceinline__ void upk(ull v, float& lo, float& hi) {
    asm("mov.b64 {%0,%1},%2;" : "=f"(lo), "=f"(hi) : "l"(v));
}
__device__ __forceinline__ ull ffma2(ull a, ull b, ull c) {
    ull d; asm("fma.rn.f32x2 %0,%1,%2,%3;" : "=l"(d) : "l"(a), "l"(b), "l"(c)); return d;
}
__device__ __forceinline__ ull fadd2(ull a, ull b) {
    ull d; asm("add.rn.f32x2 %0,%1,%2;" : "=l"(d) : "l"(a), "l"(b)); return d;
}

// ---- index load honoring runtime dtype flag ----
__device__ __forceinline__ int ld_idx(const void* ei, long long i, int is64) {
    if (is64) return (int)((const long long*)ei)[i];
    return ((const int*)ei)[i];
}

// ---------------------------------------------------------------------------
// dtype sniff: for int64 little-endian indices in [0,N), every odd 32-bit word
// is zero. For int32 data, P(64 consecutive odd words all zero) ~ (1/N)^64 ~ 0.
// ---------------------------------------------------------------------------
__global__ void kdetect(const unsigned int* __restrict__ w, int E) {
    if (threadIdx.x == 0) {
        int is64 = 1;
        int n = E < 64 ? E : 64;
        for (int i = 0; i < n; i++)
            if (w[2 * i + 1] != 0u) { is64 = 0; break; }
        g_is64 = is64;
    }
}

__global__ void kzero(int N) {
    int i = blockIdx.x * blockDim.x + threadIdx.x;
    if (i < N) g_count[i] = 0;
}

__global__ void khist(const void* __restrict__ ei, int E) {
    int e = blockIdx.x * blockDim.x + threadIdx.x;
    if (e >= E) return;
    int dst = ld_idx(ei, (long long)E + e, g_is64);
    atomicAdd(&g_count[dst], 1);
}

// single-block exclusive scan over g_count -> g_rowptr / g_cursor
__global__ void kscan(int N) {
    __shared__ int sp[1024];
    int tid = threadIdx.x;
    int chunk = (N + 1023) >> 10;
    int beg = tid * chunk;
    int end = min(beg + chunk, N);
    int s = 0;
    for (int i = beg; i < end; i++) s += g_count[i];
    sp[tid] = s;
    __syncthreads();
    for (int off = 1; off < 1024; off <<= 1) {
        int v = (tid >= off) ? sp[tid - off] : 0;
        __syncthreads();
        sp[tid] += v;
        __syncthreads();
    }
    int run = (tid == 0) ? 0 : sp[tid - 1];
    for (int i = beg; i < end; i++) {
        g_rowptr[i] = run;
        g_cursor[i] = run;
        run += g_count[i];
    }
    if (end == N) g_rowptr[N] = run;  // tail threads write identical total
}

__global__ void kscatter(const void* __restrict__ ei, int E) {
    int e = blockIdx.x * blockDim.x + threadIdx.x;
    if (e >= E) return;
    int dst = ld_idx(ei, (long long)E + e, g_is64);
    int pos = atomicAdd(&g_cursor[dst], 1);
    g_eperm[pos] = e;
}

// ---------------------------------------------------------------------------
// Node transform: xl = x@Wl+bl, xr = x@Wr+br. Tile: 32 nodes x 256 out-cols.
// Thread t owns out-column t (t<128 -> xl col t, else xr col t-128) for all
// 32 nodes, accumulated as 16 packed f32x2 pairs. W staged in smem in 16-row
// K-chunks (static smem stays < 48KB). x tile stored k-major (pad 36) so the
// inner loads are warp-broadcast LDS.128. NOTE: xs is indexed by the GLOBAL
// K-row (kc*16+k) — ws is restaged per chunk so local k is fine there.
// ---------------------------------------------------------------------------
__global__ __launch_bounds__(256) void k_gemm(
    const float* __restrict__ x,
    const float* __restrict__ Wl, const float* __restrict__ bl,
    const float* __restrict__ Wr, const float* __restrict__ br, int N)
{
    __shared__ __align__(16) float xs[128 * 36];   // 18 KB, xs[k*36+n]
    __shared__ __align__(16) float ws[16 * 256];   // 16 KB, ws[k*256+j]
    int tid = threadIdx.x;
    int nb = blockIdx.x * 32;

    for (int i = tid; i < 32 * 128; i += 256) {
        int n = i >> 7, k = i & 127;
        int node = nb + n;
        xs[k * 36 + n] = (node < N) ? x[(size_t)node * 128 + k] : 0.f;
    }

    ull acc[16];
#pragma unroll
    for (int q = 0; q < 16; q++) acc[q] = 0ull;

    for (int kc = 0; kc < 8; kc++) {
        __syncthreads();
        for (int i = tid; i < 16 * 128; i += 256) {
            int k = i >> 7, j = i & 127;
            int krow = kc * 16 + k;
            ws[k * 256 + j]       = Wl[(size_t)krow * 128 + j];
            ws[k * 256 + 128 + j] = Wr[(size_t)krow * 128 + j];
        }
        __syncthreads();
#pragma unroll 1
        for (int k = 0; k < 16; k++) {
            float w = ws[k * 256 + tid];
            ull w2 = pk(w, w);
            // FIX (R1): index xs by GLOBAL K-row kc*16+k, not local k.
            const ulonglong2* xrow = (const ulonglong2*)(xs + (kc * 16 + k) * 36);
#pragma unroll
            for (int p = 0; p < 8; p++) {
                ulonglong2 v = xrow[p];           // broadcast LDS.128
                acc[2 * p]     = ffma2(v.x, w2, acc[2 * p]);
                acc[2 * p + 1] = ffma2(v.y, w2, acc[2 * p + 1]);
            }
        }
    }

    int col = tid & 127;
    float b = (tid < 128) ? bl[col] : br[col];
    float* dst = (tid < 128) ? g_xl : g_xr;
#pragma unroll 1
    for (int q = 0; q < 16; q++) {
        float a0, a1; upk(acc[q], a0, a1);
        int n0 = nb + 2 * q, n1 = n0 + 1;
        if (n0 < N) dst[(size_t)n0 * 128 + col] = a0 + b;
        if (n1 < N) dst[(size_t)n1 * 128 + col] = a1 + b;
    }
}

// ---------------------------------------------------------------------------
// Fused per-node kernel: one warp per node (grid-stride). Lane l owns
// channels 4l..4l+3. We (16x128) hoisted into 32 packed regs per lane.
// Softmax needs no max-subtraction (logit std ~1.25; exp never overflows),
// and since den is per-node constant: out = (sum_e ex_e * xl[src_e]) / den.
// Each of the 8 lanes of a head holds the full logit after 3 butterfly
// shuffles, so every lane computes its own ex and its own den — no cross-lane
// denominator exchange at all.
// ---------------------------------------------------------------------------
__global__ __launch_bounds__(256, 2) void k_fused(
    const void*  __restrict__ ei,
    const float* __restrict__ ea,
    const float* __restrict__ We,
    const float* __restrict__ attw,
    const float* __restrict__ bias,
    const float* __restrict__ gamma,
    const float* __restrict__ beta,
    const float* __restrict__ x,
    float* __restrict__ out, int N)
{
    const int lane = threadIdx.x & 31;
    const int wid = (blockIdx.x * blockDim.x + threadIdx.x) >> 5;
    const int nwarps = (gridDim.x * blockDim.x) >> 5;
    const int is64 = g_is64;

    // hoist We columns for this lane's 4 channels: wA[d]={We[d][4l],We[d][4l+1]}
    ull wA[16], wB[16];
#pragma unroll
    for (int d = 0; d < 16; d++) {
        float4 w = *(const float4*)(We + (size_t)d * 128 + lane * 4);
        wA[d] = pk(w.x, w.y);
        wB[d] = pk(w.z, w.w);
    }
    float4 at4 = *(const float4*)(attw + lane * 4);   // att flat [h*C+c] == channel j
    float4 b4  = *(const float4*)(bias + lane * 4);
    float4 g4  = *(const float4*)(gamma + lane * 4);
    float4 be4 = *(const float4*)(beta + lane * 4);

    for (int n = wid; n < N; n += nwarps) {
        int beg = g_rowptr[n];
        int end = g_rowptr[n + 1];
        float4 xr4 = *(const float4*)(g_xr + (size_t)n * 128 + lane * 4);
        ull xr01 = pk(xr4.x, xr4.y), xr23 = pk(xr4.z, xr4.w);

        ull num01 = 0ull, num23 = 0ull;
        float den = 0.f;

#pragma unroll 1
        for (int i = beg; i < end; i++) {
            int eid = g_eperm[i];                          // warp-uniform
            int src = ld_idx(ei, eid, is64);               // warp-uniform
            const float4* eap = (const float4*)(ea + (size_t)eid * 16);
            float4 e0 = eap[0], e1 = eap[1], e2 = eap[2], e3 = eap[3];
            float aa[16] = { e0.x, e0.y, e0.z, e0.w, e1.x, e1.y, e1.z, e1.w,
                             e2.x, e2.y, e2.z, e2.w, e3.x, e3.y, e3.z, e3.w };
            float4 xl4 = *(const float4*)(g_xl + (size_t)src * 128 + lane * 4);

            ull ef01 = 0ull, ef23 = 0ull;
#pragma unroll
            for (int d = 0; d < 16; d++) {
                ull ad = pk(aa[d], aa[d]);
                ef01 = ffma2(ad, wA[d], ef01);
                ef23 = ffma2(ad, wB[d], ef23);
            }
            ull xl01 = pk(xl4.x, xl4.y), xl23 = pk(xl4.z, xl4.w);
            ull s01 = fadd2(fadd2(xl01, xr01), ef01);
            ull s23 = fadd2(fadd2(xl23, xr23), ef23);
            float u0, u1, u2, u3;
            upk(s01, u0, u1); upk(s23, u2, u3);
            u0 = fmaxf(u0, 0.2f * u0);   // leaky_relu, slope 0.2
            u1 = fmaxf(u1, 0.2f * u1);
            u2 = fmaxf(u2, 0.2f * u2);
            u3 = fmaxf(u3, 0.2f * u3);
            float t = u0 * at4.x + u1 * at4.y + u2 * at4.z + u3 * at4.w;
            // reduce within 8-lane head group (xor 1,2,4 stays in-group)
            t += __shfl_xor_sync(0xffffffffu, t, 1);
            t += __shfl_xor_sync(0xffffffffu, t, 2);
            t += __shfl_xor_sync(0xffffffffu, t, 4);
            float ex = __expf(t);
            den += ex;
            ull ex2 = pk(ex, ex);
            num01 = ffma2(ex2, xl01, num01);
            num23 = ffma2(ex2, xl23, num23);
        }

        float invd = 1.f / (den + 1e-16f);
        float o0, o1, o2, o3;
        upk(num01, o0, o1); upk(num23, o2, o3);
        o0 = o0 * invd + b4.x;
        o1 = o1 * invd + b4.y;
        o2 = o2 * invd + b4.z;
        o3 = o3 * invd + b4.w;
        // exact GELU: 0.5*x*(1+erf(x/sqrt(2)))
        const float inv_sqrt2 = 0.70710678118654752f;
        o0 = 0.5f * o0 * (1.f + erff(o0 * inv_sqrt2));
        o1 = 0.5f * o1 * (1.f + erff(o1 * inv_sqrt2));
        o2 = 0.5f * o2 * (1.f + erff(o2 * inv_sqrt2));
        o3 = 0.5f * o3 * (1.f + erff(o3 * inv_sqrt2));
        float4 x4 = *(const float4*)(x + (size_t)n * 128 + lane * 4);
        float v0 = o0 + x4.x, v1 = o1 + x4.y, v2 = o2 + x4.z, v3 = o3 + x4.w;

        float s = v0 + v1 + v2 + v3;
        float q = v0 * v0 + v1 * v1 + v2 * v2 + v3 * v3;
#pragma unroll
        for (int m = 16; m >= 1; m >>= 1) {
            s += __shfl_xor_sync(0xffffffffu, s, m);
            q += __shfl_xor_sync(0xffffffffu, q, m);
        }
        float mu = s * (1.f / 128.f);
        float var = q * (1.f / 128.f) - mu * mu;
        float rs = rsqrtf(var + 1e-5f);
        float4 y;
        y.x = (v0 - mu) * rs * g4.x + be4.x;
        y.y = (v1 - mu) * rs * g4.y + be4.y;
        y.z = (v2 - mu) * rs * g4.z + be4.z;
        y.w = (v3 - mu) * rs * g4.w + be4.w;
        *(float4*)(out + (size_t)n * 128 + lane * 4) = y;
    }
}

// ---------------------------------------------------------------------------
extern "C" void kernel_launch(void* const* d_in, const int* in_sizes, int n_in,
                              void* d_out, int out_size)
{
    const float* x    = (const float*)d_in[0];
    const void*  ei   = d_in[1];
    const float* ea   = (const float*)d_in[2];
    const float* Wl   = (const float*)d_in[3];
    const float* bl   = (const float*)d_in[4];
    const float* Wr   = (const float*)d_in[5];
    const float* br   = (const float*)d_in[6];
    const float* We   = (const float*)d_in[7];
    const float* att  = (const float*)d_in[8];
    const float* bias = (const float*)d_in[9];
    const float* gam  = (const float*)d_in[10];
    const float* bet  = (const float*)d_in[11];

    int N = in_sizes[0] / 128;
    int E = in_sizes[1] / 2;

    kdetect<<<1, 32>>>((const unsigned int*)ei, E);
    kzero<<<(N + 255) / 256, 256>>>(N);
    khist<<<(E + 255) / 256, 256>>>(ei, E);
    kscan<<<1, 1024>>>(N);
    kscatter<<<(E + 255) / 256, 256>>>(ei, E);
    k_gemm<<<(N + 31) / 32, 256>>>(x, Wl, bl, Wr, br, N);
    k_fused<<<1480, 256>>>(ei, ea, We, att, bias, gam, bet, x, (float*)d_out, N);
}

// round 3
// speedup vs baseline: 1.2066x; 1.2066x over previous
#include <cuda_runtime.h>
#include <math.h>

// ---------------------------------------------------------------------------
// GATv2Conv layer. N=50000, E=800000, D=128, H=4, C=32.
//   kdetect  : int64 vs int32 edge_index sniffing (parallel ballot)
//   kzero    : zero per-dst degree histogram
//   khist    : degree histogram (int atomics)
//   kscan1/2/3: coalesced 3-phase exclusive scan -> rowptr + cursor
//   kscatter : build dst-CSR payload {src, eid} (int2)
//   k_gemm   : xl = x@Wl+bl, xr = x@Wr+br  (f32x2 packed FMA, smem-tiled)
//   k_fused  : per-node edge loop (e_feat matvec + leakyrelu + att dot + exp
//              + running num/den), softmax-free normalize, bias, exact GELU,
//              residual, warp LayerNorm, store
// ---------------------------------------------------------------------------

#define MAX_N 50000
#define MAX_E 800000
#define SCAN_B 1024
#define NBLK ((MAX_N + SCAN_B - 1) / SCAN_B)   // 49

typedef unsigned long long ull;

__device__ int   g_is64;
__device__ float g_xl[(size_t)MAX_N * 128];
__device__ float g_xr[(size_t)MAX_N * 128];
__device__ int   g_count[MAX_N];
__device__ int   g_rowptr[MAX_N + 1];
__device__ int   g_cursor[MAX_N];
__device__ int2  g_edata[MAX_E];     // CSR payload: {src, eid}
__device__ int   g_blocksum[64];
__device__ int   g_blockoff[64];

// ---- packed f32x2 helpers (Blackwell) ----
__device__ __forceinline__ ull pk(float lo, float hi) {
    ull r; asm("mov.b64 %0,{%1,%2};" : "=l"(r) : "f"(lo), "f"(hi)); return r;
}
__device__ __forceinline__ void upk(ull v, float& lo, float& hi) {
    asm("mov.b64 {%0,%1},%2;" : "=f"(lo), "=f"(hi) : "l"(v));
}
__device__ __forceinline__ ull ffma2(ull a, ull b, ull c) {
    ull d; asm("fma.rn.f32x2 %0,%1,%2,%3;" : "=l"(d) : "l"(a), "l"(b), "l"(c)); return d;
}
__device__ __forceinline__ ull fadd2(ull a, ull b) {
    ull d; asm("add.rn.f32x2 %0,%1,%2;" : "=l"(d) : "l"(a), "l"(b)); return d;
}

__device__ __forceinline__ int ld_idx(const void* ei, long long i, int is64) {
    if (is64) return (int)((const long long*)ei)[i];
    return ((const int*)ei)[i];
}

// ---------------------------------------------------------------------------
// dtype sniff (parallel): int64 indices in [0,N) have all odd 32-bit words 0.
// ---------------------------------------------------------------------------
__global__ void kdetect(const unsigned int* __restrict__ w, int E) {
    int lane = threadIdx.x;
    int bad = 0;
    int n = E < 64 ? E : 64;
    for (int j = lane; j < n; j += 32)
        if (w[2 * j + 1] != 0u) bad = 1;
    unsigned any = __ballot_sync(0xffffffffu, bad);
    if (lane == 0) g_is64 = (any == 0u);
}

__global__ void kzero(int N) {
    int i = blockIdx.x * blockDim.x + threadIdx.x;
    if (i < N) g_count[i] = 0;
}

__global__ void khist(const void* __restrict__ ei, int E) {
    int e = blockIdx.x * blockDim.x + threadIdx.x;
    if (e >= E) return;
    int dst = ld_idx(ei, (long long)E + e, g_is64);
    atomicAdd(&g_count[dst], 1);
}

// ---- 3-phase coalesced exclusive scan over g_count ----
__global__ void kscan1(int N) {
    __shared__ int red[32];
    int t = threadIdx.x;
    int idx = blockIdx.x * SCAN_B + t;
    int v = (idx < N) ? g_count[idx] : 0;
#pragma unroll
    for (int o = 16; o >= 1; o >>= 1) v += __shfl_down_sync(0xffffffffu, v, o);
    if ((t & 31) == 0) red[t >> 5] = v;
    __syncthreads();
    if (t < 32) {
        int u = red[t];
#pragma unroll
        for (int o = 16; o >= 1; o >>= 1) u += __shfl_down_sync(0xffffffffu, u, o);
        if (t == 0) g_blocksum[blockIdx.x] = u;
    }
}

__global__ void kscan2(int nb) {
    if (threadIdx.x == 0) {
        int run = 0;
        for (int i = 0; i < nb; i++) { int c = g_blocksum[i]; g_blockoff[i] = run; run += c; }
    }
}

__global__ void kscan3(int N) {
    __shared__ int wsum[32];
    int t = threadIdx.x;
    int lane = t & 31, w = t >> 5;
    int idx = blockIdx.x * SCAN_B + t;
    int v = (idx < N) ? g_count[idx] : 0;
    int s = v;
#pragma unroll
    for (int o = 1; o < 32; o <<= 1) {
        int u = __shfl_up_sync(0xffffffffu, s, o);
        if (lane >= o) s += u;
    }
    if (lane == 31) wsum[w] = s;
    __syncthreads();
    if (w == 0) {
        int ws = wsum[lane];
#pragma unroll
        for (int o = 1; o < 32; o <<= 1) {
            int u = __shfl_up_sync(0xffffffffu, ws, o);
            if (lane >= o) ws += u;
        }
        wsum[lane] = ws;
    }
    __syncthreads();
    int excl = s - v + (w ? wsum[w - 1] : 0) + g_blockoff[blockIdx.x];
    if (idx < N) {
        g_rowptr[idx] = excl;
        g_cursor[idx] = excl;
        if (idx == N - 1) g_rowptr[N] = excl + v;
    }
}

// scatter CSR payload: {src, eid} so k_fused needs no dependent index hops
__global__ void kscatter(const void* __restrict__ ei, int E) {
    int e = blockIdx.x * blockDim.x + threadIdx.x;
    if (e >= E) return;
    int is64 = g_is64;
    int dst = ld_idx(ei, (long long)E + e, is64);
    int src = ld_idx(ei, e, is64);
    int pos = atomicAdd(&g_cursor[dst], 1);
    g_edata[pos] = make_int2(src, e);
}

// ---------------------------------------------------------------------------
// Node transform: xl = x@Wl+bl, xr = x@Wr+br. Tile: 32 nodes x 256 out-cols.
// ---------------------------------------------------------------------------
__global__ __launch_bounds__(256) void k_gemm(
    const float* __restrict__ x,
    const float* __restrict__ Wl, const float* __restrict__ bl,
    const float* __restrict__ Wr, const float* __restrict__ br, int N)
{
    __shared__ __align__(16) float xs[128 * 36];   // xs[k*36+n]
    __shared__ __align__(16) float ws[16 * 256];   // ws[k*256+j]
    int tid = threadIdx.x;
    int nb = blockIdx.x * 32;

    for (int i = tid; i < 32 * 128; i += 256) {
        int n = i >> 7, k = i & 127;
        int node = nb + n;
        xs[k * 36 + n] = (node < N) ? x[(size_t)node * 128 + k] : 0.f;
    }

    ull acc[16];
#pragma unroll
    for (int q = 0; q < 16; q++) acc[q] = 0ull;

    for (int kc = 0; kc < 8; kc++) {
        __syncthreads();
        for (int i = tid; i < 16 * 128; i += 256) {
            int k = i >> 7, j = i & 127;
            int krow = kc * 16 + k;
            ws[k * 256 + j]       = Wl[(size_t)krow * 128 + j];
            ws[k * 256 + 128 + j] = Wr[(size_t)krow * 128 + j];
        }
        __syncthreads();
#pragma unroll 1
        for (int k = 0; k < 16; k++) {
            float w = ws[k * 256 + tid];
            ull w2 = pk(w, w);
            const ulonglong2* xrow = (const ulonglong2*)(xs + (kc * 16 + k) * 36);
#pragma unroll
            for (int p = 0; p < 8; p++) {
                ulonglong2 v = xrow[p];           // broadcast LDS.128
                acc[2 * p]     = ffma2(v.x, w2, acc[2 * p]);
                acc[2 * p + 1] = ffma2(v.y, w2, acc[2 * p + 1]);
            }
        }
    }

    int col = tid & 127;
    float b = (tid < 128) ? bl[col] : br[col];
    float* dst = (tid < 128) ? g_xl : g_xr;
#pragma unroll 1
    for (int q = 0; q < 16; q++) {
        float a0, a1; upk(acc[q], a0, a1);
        int n0 = nb + 2 * q, n1 = n0 + 1;
        if (n0 < N) dst[(size_t)n0 * 128 + col] = a0 + b;
        if (n1 < N) dst[(size_t)n1 * 128 + col] = a1 + b;
    }
}

// ---------------------------------------------------------------------------
// Fused per-node kernel: one warp per node (grid-stride). Lane l owns
// channels 4l..4l+3. We (16x128) hoisted into 32 packed regs per lane.
// Softmax without max-subtraction (logit std ~1.25, exp can't overflow);
// den is per-node so out = (sum_e ex_e * xl[src_e]) / den. The 3 butterfly
// shuffles give every lane of an 8-lane head group the full logit.
// ---------------------------------------------------------------------------
__global__ __launch_bounds__(256, 2) void k_fused(
    const float* __restrict__ ea,
    const float* __restrict__ We,
    const float* __restrict__ attw,
    const float* __restrict__ bias,
    const float* __restrict__ gamma,
    const float* __restrict__ beta,
    const float* __restrict__ x,
    float* __restrict__ out, int N)
{
    const int lane = threadIdx.x & 31;
    const int wid = (blockIdx.x * blockDim.x + threadIdx.x) >> 5;
    const int nwarps = (gridDim.x * blockDim.x) >> 5;

    // hoist We columns for this lane's 4 channels
    ull wA[16], wB[16];
#pragma unroll
    for (int d = 0; d < 16; d++) {
        float4 w = *(const float4*)(We + (size_t)d * 128 + lane * 4);
        wA[d] = pk(w.x, w.y);
        wB[d] = pk(w.z, w.w);
    }
    float4 at4 = *(const float4*)(attw + lane * 4);   // att flat [h*C+c]

    for (int n = wid; n < N; n += nwarps) {
        int beg = g_rowptr[n];
        int end = g_rowptr[n + 1];
        float4 xr4 = *(const float4*)(g_xr + (size_t)n * 128 + lane * 4);
        ull xr01 = pk(xr4.x, xr4.y), xr23 = pk(xr4.z, xr4.w);

        ull num01 = 0ull, num23 = 0ull;
        float den = 0.f;

        int2 ed = (beg < end) ? g_edata[beg] : make_int2(0, 0);

#pragma unroll 1
        for (int i = beg; i < end; i++) {
            const float4* eap = (const float4*)(ea + (size_t)ed.y * 16);
            float4 xl4 = *(const float4*)(g_xl + (size_t)ed.x * 128 + lane * 4);
            float4 e0 = eap[0], e1 = eap[1], e2 = eap[2], e3 = eap[3];
            if (i + 1 < end) ed = g_edata[i + 1];   // prefetch next edge

            ull ef01 = 0ull, ef23 = 0ull;
            {
                ull a;
                a = pk(e0.x, e0.x); ef01 = ffma2(a, wA[0],  ef01); ef23 = ffma2(a, wB[0],  ef23);
                a = pk(e0.y, e0.y); ef01 = ffma2(a, wA[1],  ef01); ef23 = ffma2(a, wB[1],  ef23);
                a = pk(e0.z, e0.z); ef01 = ffma2(a, wA[2],  ef01); ef23 = ffma2(a, wB[2],  ef23);
                a = pk(e0.w, e0.w); ef01 = ffma2(a, wA[3],  ef01); ef23 = ffma2(a, wB[3],  ef23);
                a = pk(e1.x, e1.x); ef01 = ffma2(a, wA[4],  ef01); ef23 = ffma2(a, wB[4],  ef23);
                a = pk(e1.y, e1.y); ef01 = ffma2(a, wA[5],  ef01); ef23 = ffma2(a, wB[5],  ef23);
                a = pk(e1.z, e1.z); ef01 = ffma2(a, wA[6],  ef01); ef23 = ffma2(a, wB[6],  ef23);
                a = pk(e1.w, e1.w); ef01 = ffma2(a, wA[7],  ef01); ef23 = ffma2(a, wB[7],  ef23);
                a = pk(e2.x, e2.x); ef01 = ffma2(a, wA[8],  ef01); ef23 = ffma2(a, wB[8],  ef23);
                a = pk(e2.y, e2.y); ef01 = ffma2(a, wA[9],  ef01); ef23 = ffma2(a, wB[9],  ef23);
                a = pk(e2.z, e2.z); ef01 = ffma2(a, wA[10], ef01); ef23 = ffma2(a, wB[10], ef23);
                a = pk(e2.w, e2.w); ef01 = ffma2(a, wA[11], ef01); ef23 = ffma2(a, wB[11], ef23);
                a = pk(e3.x, e3.x); ef01 = ffma2(a, wA[12], ef01); ef23 = ffma2(a, wB[12], ef23);
                a = pk(e3.y, e3.y); ef01 = ffma2(a, wA[13], ef01); ef23 = ffma2(a, wB[13], ef23);
                a = pk(e3.z, e3.z); ef01 = ffma2(a, wA[14], ef01); ef23 = ffma2(a, wB[14], ef23);
                a = pk(e3.w, e3.w); ef01 = ffma2(a, wA[15], ef01); ef23 = ffma2(a, wB[15], ef23);
            }
            ull xl01 = pk(xl4.x, xl4.y), xl23 = pk(xl4.z, xl4.w);
            ull s01 = fadd2(fadd2(xl01, xr01), ef01);
            ull s23 = fadd2(fadd2(xl23, xr23), ef23);
            float u0, u1, u2, u3;
            upk(s01, u0, u1); upk(s23, u2, u3);
            u0 = fmaxf(u0, 0.2f * u0);   // leaky_relu, slope 0.2
            u1 = fmaxf(u1, 0.2f * u1);
            u2 = fmaxf(u2, 0.2f * u2);
            u3 = fmaxf(u3, 0.2f * u3);
            float t = u0 * at4.x + u1 * at4.y + u2 * at4.z + u3 * at4.w;
            t += __shfl_xor_sync(0xffffffffu, t, 1);
            t += __shfl_xor_sync(0xffffffffu, t, 2);
            t += __shfl_xor_sync(0xffffffffu, t, 4);
            float ex = __expf(t);
            den += ex;
            ull ex2 = pk(ex, ex);
            num01 = ffma2(ex2, xl01, num01);
            num23 = ffma2(ex2, xl23, num23);
        }

        // ---- epilogue (per-node constants loaded here to cut live regs) ----
        float4 b4  = *(const float4*)(bias  + lane * 4);
        float4 g4  = *(const float4*)(gamma + lane * 4);
        float4 be4 = *(const float4*)(beta  + lane * 4);

        float invd = 1.f / (den + 1e-16f);
        float o0, o1, o2, o3;
        upk(num01, o0, o1); upk(num23, o2, o3);
        o0 = o0 * invd + b4.x;
        o1 = o1 * invd + b4.y;
        o2 = o2 * invd + b4.z;
        o3 = o3 * invd + b4.w;
        const float inv_sqrt2 = 0.70710678118654752f;
        o0 = 0.5f * o0 * (1.f + erff(o0 * inv_sqrt2));
        o1 = 0.5f * o1 * (1.f + erff(o1 * inv_sqrt2));
        o2 = 0.5f * o2 * (1.f + erff(o2 * inv_sqrt2));
        o3 = 0.5f * o3 * (1.f + erff(o3 * inv_sqrt2));
        float4 x4 = *(const float4*)(x + (size_t)n * 128 + lane * 4);
        float v0 = o0 + x4.x, v1 = o1 + x4.y, v2 = o2 + x4.z, v3 = o3 + x4.w;

        float s = v0 + v1 + v2 + v3;
        float q = v0 * v0 + v1 * v1 + v2 * v2 + v3 * v3;
#pragma unroll
        for (int m = 16; m >= 1; m >>= 1) {
            s += __shfl_xor_sync(0xffffffffu, s, m);
            q += __shfl_xor_sync(0xffffffffu, q, m);
        }
        float mu = s * (1.f / 128.f);
        float var = q * (1.f / 128.f) - mu * mu;
        float rs = rsqrtf(var + 1e-5f);
        float4 y;
        y.x = (v0 - mu) * rs * g4.x + be4.x;
        y.y = (v1 - mu) * rs * g4.y + be4.y;
        y.z = (v2 - mu) * rs * g4.z + be4.z;
        y.w = (v3 - mu) * rs * g4.w + be4.w;
        *(float4*)(out + (size_t)n * 128 + lane * 4) = y;
    }
}

// ---------------------------------------------------------------------------
extern "C" void kernel_launch(void* const* d_in, const int* in_sizes, int n_in,
                              void* d_out, int out_size)
{
    const float* x    = (const float*)d_in[0];
    const void*  ei   = d_in[1];
    const float* ea   = (const float*)d_in[2];
    const float* Wl   = (const float*)d_in[3];
    const float* bl   = (const float*)d_in[4];
    const float* Wr   = (const float*)d_in[5];
    const float* br   = (const float*)d_in[6];
    const float* We   = (const float*)d_in[7];
    const float* att  = (const float*)d_in[8];
    const float* bias = (const float*)d_in[9];
    const float* gam  = (const float*)d_in[10];
    const float* bet  = (const float*)d_in[11];

    int N = in_sizes[0] / 128;
    int E = in_sizes[1] / 2;
    int nb = (N + SCAN_B - 1) / SCAN_B;

    kdetect<<<1, 32>>>((const unsigned int*)ei, E);
    kzero<<<(N + 255) / 256, 256>>>(N);
    khist<<<(E + 255) / 256, 256>>>(ei, E);
    kscan1<<<nb, SCAN_B>>>(N);
    kscan2<<<1, 32>>>(nb);
    kscan3<<<nb, SCAN_B>>>(N);
    kscatter<<<(E + 255) / 256, 256>>>(ei, E);
    k_gemm<<<(N + 31) / 32, 256>>>(x, Wl, bl, Wr, br, N);
    k_fused<<<1480, 256>>>(ea, We, att, bias, gam, bet, x, (float*)d_out, N);
}